// round 2
// baseline (speedup 1.0000x reference)
#include <cuda_runtime.h>
#include <cuda_bf16.h>
#include <cstddef>

// CEmbedder: 36 independent scalar-input MLPs.
//   h[b,i,k] = leaky(x[b,i]*W1[i,k] + b1[i,k])         (K = 512)
//   out[b,i,d] = sum_k h[b,i,k]*W2[i,k,d] + b2[i,d]    (D = 1024, B = 2048)
//
// Batched SGEMM, 36 x (M=2048, K=512, N=1024). A tile synthesized in SMEM
// from x/W1/b1 (rank-1 + bias + leaky), so A costs no HBM traffic.

#define BATCH     2048
#define NBRANCH   36
#define KDIM      512
#define NDIM      1024
#define NEG_SLOPE 0.01f

#define BM 128
#define BN 128
#define BK 16
#define TM 8
#define TN 8
#define NTHREADS 256

__global__ __launch_bounds__(NTHREADS, 2)
void cembedder_kernel(const float* __restrict__ x,
                      const float* __restrict__ W1,
                      const float* __restrict__ b1,
                      const float* __restrict__ W2,
                      const float* __restrict__ b2,
                      float* __restrict__ out)
{
    const int nblk = blockIdx.x;   // 0..7   (N tiles)
    const int mblk = blockIdx.y;   // 0..15  (M tiles)
    const int br   = blockIdx.z;   // 0..35  (branch)

    __shared__ float xs[BM];
    __shared__ float As[BK][BM];
    __shared__ float Bs[BK][BN];

    const int tid = threadIdx.x;
    const int ty  = tid / 16;      // 0..15 -> M sub-tile
    const int tx  = tid % 16;      // 0..15 -> N sub-tile

    // Load the 128 scalar inputs for this M tile (stride NBRANCH in x).
    if (tid < BM) {
        xs[tid] = x[(size_t)(mblk * BM + tid) * NBRANCH + br];
    }

    const float* W2i = W2 + (size_t)br * KDIM * NDIM;
    const float* W1i = W1 + br * KDIM;
    const float* b1i = b1 + br * KDIM;

    float acc[TM][TN];
    #pragma unroll
    for (int m = 0; m < TM; m++)
        #pragma unroll
        for (int n = 0; n < TN; n++)
            acc[m][n] = 0.0f;

    __syncthreads();

    for (int k0 = 0; k0 < KDIM; k0 += BK) {
        // ---- Load B tile: W2[br, k0:k0+16, n0:n0+128]  (2 x float4 / thread)
        {
            const int off = tid * 8;          // 0..2040
            const int kr  = off / BN;         // 0..15
            const int nc  = off % BN;         // multiple of 8
            const float4* src = reinterpret_cast<const float4*>(
                W2i + (size_t)(k0 + kr) * NDIM + nblk * BN + nc);
            *reinterpret_cast<float4*>(&Bs[kr][nc])     = __ldg(src);
            *reinterpret_cast<float4*>(&Bs[kr][nc + 4]) = __ldg(src + 1);
        }
        // ---- Synthesize A tile: leaky(xs[m]*W1[k] + b1[k])  (8 elems / thread)
        {
            const int off = tid * 8;
            const int kr  = off / BM;         // 0..15
            const int mc  = off % BM;         // multiple of 8
            const float w  = __ldg(W1i + k0 + kr);  // broadcast, L1-hot
            const float bb = __ldg(b1i + k0 + kr);
            #pragma unroll
            for (int j = 0; j < 8; j++) {
                float h = fmaf(xs[mc + j], w, bb);
                As[kr][mc + j] = (h >= 0.0f) ? h : NEG_SLOPE * h;
            }
        }
        __syncthreads();

        // ---- 128x128x16 FFMA micro-kernel, 8x8 per thread
        #pragma unroll
        for (int k = 0; k < BK; k++) {
            float a[TM], b[TN];
            #pragma unroll
            for (int m = 0; m < TM; m += 4)
                *reinterpret_cast<float4*>(&a[m]) =
                    *reinterpret_cast<const float4*>(&As[k][ty * TM + m]);
            #pragma unroll
            for (int n = 0; n < TN; n += 4)
                *reinterpret_cast<float4*>(&b[n]) =
                    *reinterpret_cast<const float4*>(&Bs[k][tx * TN + n]);
            #pragma unroll
            for (int m = 0; m < TM; m++)
                #pragma unroll
                for (int n = 0; n < TN; n++)
                    acc[m][n] = fmaf(a[m], b[n], acc[m][n]);
        }
        __syncthreads();
    }

    // ---- Epilogue: add b2, store fp32 (float4)
    const float* b2i = b2 + br * NDIM;
    const int nbase = nblk * BN + tx * TN;
    #pragma unroll
    for (int m = 0; m < TM; m++) {
        const int row = mblk * BM + ty * TM + m;
        float* o = out + ((size_t)row * NBRANCH + br) * NDIM + nbase;
        #pragma unroll
        for (int n = 0; n < TN; n += 4) {
            float4 v;
            v.x = acc[m][n + 0] + b2i[nbase + n + 0];
            v.y = acc[m][n + 1] + b2i[nbase + n + 1];
            v.z = acc[m][n + 2] + b2i[nbase + n + 2];
            v.w = acc[m][n + 3] + b2i[nbase + n + 3];
            *reinterpret_cast<float4*>(o + n) = v;
        }
    }
}

extern "C" void kernel_launch(void* const* d_in, const int* in_sizes, int n_in,
                              void* d_out, int out_size)
{
    const float* x  = (const float*)d_in[0];
    const float* W1 = (const float*)d_in[1];
    const float* b1 = (const float*)d_in[2];
    const float* W2 = (const float*)d_in[3];
    const float* b2 = (const float*)d_in[4];
    float* out = (float*)d_out;

    dim3 grid(NDIM / BN, BATCH / BM, NBRANCH);  // (8, 16, 36)
    cembedder_kernel<<<grid, NTHREADS>>>(x, W1, b1, W2, b2, out);
}

// round 4
// speedup vs baseline: 6.6996x; 6.6996x over previous
#include <cuda_runtime.h>
#include <cstdint>
#include <cstddef>
#include <math_constants.h>

// CEmbedder, piecewise-linear reformulation.
// h[m,k] = leaky(x_m*w1_k + b1_k) = g * (x_m*w1_k + b1_k), g in {1, 0.01}.
// For fixed branch, g flips for k exactly once as x crosses t_k = -b1_k/w1_k.
// => out[m,:] = x_m * alpha(x_m) + beta(x_m), alpha/beta piecewise-constant
//    1024-vectors with <=512 breakpoints. Sweep rows in x-sorted order,
//    maintaining alpha/beta with rank-1 updates. O(B*D) output work only.

#define NBRANCH 36
#define BATCH   2048
#define KDIM    512
#define NDIM    1024

#define DCHUNK  256         // columns per scan CTA
#define NT1     256         // threads per scan CTA (1 column each)
#define NDC     (NDIM / DCHUNK)   // 4 CTAs per branch

// ---- scratch (__device__ globals; no allocation allowed) ----
__device__ float g_evt[NBRANCH][KDIM];   // sorted thresholds
__device__ float g_eva[NBRANCH][KDIM];   // dir * w1_k   (alpha delta coef)
__device__ float g_evb[NBRANCH][KDIM];   // dir * b1_k   (beta delta coef)
__device__ int   g_evk[NBRANCH][KDIM];   // original k per sorted event
__device__ float g_ga [NBRANCH][KDIM];   // g0 * w1_k    (base coef)
__device__ float g_gb [NBRANCH][KDIM];   // g0 * b1_k
__device__ float g_xs [NBRANCH][BATCH];  // x sorted ascending
__device__ int   g_rid[NBRANCH][BATCH];  // row id per sorted x

__device__ __forceinline__ uint32_t smem_u32(const void* p) {
    uint32_t a;
    asm("{ .reg .u64 t; cvta.to.shared.u64 t, %1; cvt.u32.u64 %0, t; }"
        : "=r"(a) : "l"(p));
    return a;
}

// ============ K0: per-branch setup (thresholds, base coefs, sorts) =========
__global__ __launch_bounds__(256)
void setup_kernel(const float* __restrict__ x,
                  const float* __restrict__ W1,
                  const float* __restrict__ b1)
{
    const int br  = blockIdx.x;
    const int tid = threadIdx.x;

    __shared__ float ts[KDIM];
    __shared__ int   tk[KDIM];
    __shared__ float xsh[BATCH];
    __shared__ int   rsh[BATCH];

    for (int k = tid; k < KDIM; k += 256) {
        const float w  = W1[br * KDIM + k];
        const float bb = b1[br * KDIM + k];
        float t;
        if (w == 0.0f) t = CUDART_INF_F;        // no event; g fixed by b1 sign
        else           t = -bb / w;
        ts[k] = t;
        tk[k] = k;
        // state at x = -inf: h -> -inf*w ; negative iff w>0 (w==0: b<0)
        const bool  c0 = (w > 0.0f) || (w == 0.0f && bb < 0.0f);
        const float g0 = c0 ? 0.01f : 1.0f;
        g_ga[br][k] = g0 * w;
        g_gb[br][k] = g0 * bb;
    }
    for (int r = tid; r < BATCH; r += 256) {
        xsh[r] = x[(size_t)r * NBRANCH + br];
        rsh[r] = r;
    }

    // bitonic sort thresholds (512, ascending), payload = k
    for (int size = 2; size <= KDIM; size <<= 1)
        for (int stride = size >> 1; stride > 0; stride >>= 1) {
            __syncthreads();
            for (int i = tid; i < KDIM; i += 256) {
                const int j = i ^ stride;
                if (j > i) {
                    const bool up = ((i & size) == 0);
                    float a = ts[i], b = ts[j];
                    if ((a > b) == up) {
                        ts[i] = b; ts[j] = a;
                        int p = tk[i]; tk[i] = tk[j]; tk[j] = p;
                    }
                }
            }
        }
    // bitonic sort rows by x (2048, ascending), payload = row id
    for (int size = 2; size <= BATCH; size <<= 1)
        for (int stride = size >> 1; stride > 0; stride >>= 1) {
            __syncthreads();
            for (int i = tid; i < BATCH; i += 256) {
                const int j = i ^ stride;
                if (j > i) {
                    const bool up = ((i & size) == 0);
                    float a = xsh[i], b = xsh[j];
                    if ((a > b) == up) {
                        xsh[i] = b; xsh[j] = a;
                        int p = rsh[i]; rsh[i] = rsh[j]; rsh[j] = p;
                    }
                }
            }
        }
    __syncthreads();

    for (int i = tid; i < KDIM; i += 256) {
        const int   k  = tk[i];
        const float w  = W1[br * KDIM + k];
        const float bb = b1[br * KDIM + k];
        // crossing t_k upward: w>0 flips neg->pos (delta = +0.99*coef*W2),
        //                      w<0 flips pos->neg (delta = -0.99*coef*W2)
        const float dir = (w > 0.0f) ? 0.99f : -0.99f;
        g_evt[br][i] = ts[i];
        g_eva[br][i] = dir * w;
        g_evb[br][i] = dir * bb;
        g_evk[br][i] = k;
    }
    for (int r = tid; r < BATCH; r += 256) {
        g_xs [br][r] = xsh[r];
        g_rid[br][r] = rsh[r];
    }
}

// ============ K1: merged sweep (events + sorted rows) ======================
__global__ __launch_bounds__(NT1)
void scan_kernel(const float* __restrict__ W2,
                 const float* __restrict__ b2,
                 float* __restrict__ out)
{
    const int dc  = blockIdx.x;   // 0..NDC-1
    const int br  = blockIdx.y;   // 0..35
    const int tid = threadIdx.x;

    __shared__ float evt[KDIM], eva[KDIM], evb[KDIM];
    __shared__ int   evk[KDIM];
    __shared__ float gaS[KDIM], gbS[KDIM];
    __shared__ float xsS[BATCH];
    __shared__ int   ridS[BATCH];
    __shared__ float ring[8 * NT1];          // cp.async prefetch ring

    for (int i = tid; i < KDIM; i += NT1) {
        evt[i] = g_evt[br][i];  eva[i] = g_eva[br][i];
        evb[i] = g_evb[br][i];  evk[i] = g_evk[br][i];
        gaS[i] = g_ga[br][i];   gbS[i] = g_gb[br][i];
    }
    for (int r = tid; r < BATCH; r += NT1) {
        xsS[r]  = g_xs[br][r];
        ridS[r] = g_rid[br][r];
    }
    __syncthreads();

    const int d = dc * DCHUNK + tid;
    const float* w2p = W2 + (size_t)br * KDIM * NDIM + d;

    // ---- base: alpha0/beta0 = sum_k g0*{w1,b1}_k * W2[k,d]  (+ b2) ----
    float a0 = 0.f, a1 = 0.f, a2 = 0.f, a3 = 0.f;
    float c0 = 0.f, c1 = 0.f, c2 = 0.f, c3 = 0.f;
    #pragma unroll 4
    for (int k = 0; k < KDIM; k += 4) {
        const float v0 = __ldg(w2p + (size_t)(k + 0) * NDIM);
        const float v1 = __ldg(w2p + (size_t)(k + 1) * NDIM);
        const float v2 = __ldg(w2p + (size_t)(k + 2) * NDIM);
        const float v3 = __ldg(w2p + (size_t)(k + 3) * NDIM);
        a0 = fmaf(gaS[k + 0], v0, a0);  c0 = fmaf(gbS[k + 0], v0, c0);
        a1 = fmaf(gaS[k + 1], v1, a1);  c1 = fmaf(gbS[k + 1], v1, c1);
        a2 = fmaf(gaS[k + 2], v2, a2);  c2 = fmaf(gbS[k + 2], v2, c2);
        a3 = fmaf(gaS[k + 3], v3, a3);  c3 = fmaf(gbS[k + 3], v3, c3);
    }
    float alpha = (a0 + a1) + (a2 + a3);
    float beta  = (c0 + c1) + (c2 + c3) + __ldg(b2 + br * NDIM + d);

    // ---- prime 8-deep cp.async ring of W2[evk[e], d] ----
    const uint32_t rb = smem_u32(ring) + 4u * (uint32_t)tid;
    #pragma unroll
    for (int p = 0; p < 8; p++) {
        const float* src = w2p + (size_t)evk[p] * NDIM;
        asm volatile("cp.async.ca.shared.global [%0], [%1], 4;\n\t"
                     "cp.async.commit_group;"
                     :: "r"(rb + (uint32_t)(p * NT1 * 4)), "l"(src) : "memory");
    }

    // ---- merged sweep: apply events with t <= x, emit rows ----
    int ei = 0;
    for (int r = 0; r < BATCH; r++) {
        const float xr = xsS[r];
        while (ei < KDIM && evt[ei] <= xr) {
            asm volatile("cp.async.wait_group 7;" ::: "memory");
            const float w2v = ring[(ei & 7) * NT1 + tid];
            alpha = fmaf(eva[ei], w2v, alpha);
            beta  = fmaf(evb[ei], w2v, beta);
            const int kn = ei + 8;
            if (kn < KDIM) {
                const float* src = w2p + (size_t)evk[kn] * NDIM;
                asm volatile("cp.async.ca.shared.global [%0], [%1], 4;"
                             :: "r"(rb + (uint32_t)((ei & 7) * NT1 * 4)),
                                "l"(src) : "memory");
            }
            asm volatile("cp.async.commit_group;" ::: "memory");
            ei++;
        }
        const int m = ridS[r];
        out[((size_t)m * NBRANCH + br) * NDIM + d] = fmaf(xr, alpha, beta);
    }
}

extern "C" void kernel_launch(void* const* d_in, const int* in_sizes, int n_in,
                              void* d_out, int out_size)
{
    const float* x  = (const float*)d_in[0];
    const float* W1 = (const float*)d_in[1];
    const float* b1 = (const float*)d_in[2];
    const float* W2 = (const float*)d_in[3];
    const float* b2 = (const float*)d_in[4];
    float* out = (float*)d_out;

    setup_kernel<<<NBRANCH, 256>>>(x, W1, b1);
    scan_kernel<<<dim3(NDC, NBRANCH), NT1>>>(W2, b2, out);
}